// round 3
// baseline (speedup 1.0000x reference)
#include <cuda_runtime.h>
#include <math.h>

#define HH    64
#define DIMC  512     // per-axis sinusoid width
#define ODIM  256     // output dim
#define BATCH 8

#define GEMM_TILES   128    // 16 k-chunks x 4 n-tiles x 2 halves
#define NPAIR_GROUPS 1024   // 4096 (h,w) pairs / 4 per group

// C[r][o]: r<64 -> A[h][o] (W cols 0:512), r>=64 -> B[w][o] (W cols 512:1024)
__device__ float        g_C[2 * HH][ODIM];      // zero-initialized at load; re-zeroed each call
__device__ unsigned int g_gemm_done;            // release count of finished gemm tiles
__device__ unsigned int g_end_cnt;              // end tickets

__global__ __launch_bounds__(256, 6) void k_fused(const float* __restrict__ W,
                                                  float* __restrict__ out,
                                                  int nblocks) {
    const int t   = threadIdx.x;
    const int bid = blockIdx.x;

    // Reset stale end counter from the previous replay. Safe: no block can
    // arrive at g_end_cnt until the gemm barrier releases, which requires
    // block 0's own tile to finish -> strictly after this store.
    if (bid == 0 && t == 0) {
        g_end_cnt = 0;
        __threadfence();
    }

    __shared__ float Es[64][36];   // [m][k] padded
    __shared__ float Ws[32][68];   // [k][n] padded (float4-friendly)

    // ---------------- Phase 1: fused embed + split-K GEMM (blocks 0..127) ----
    if (bid < GEMM_TILES) {
        const int kc   = bid & 15;          // k-chunk (32 wide)
        const int nt   = (bid >> 4) & 3;    // n-tile (64 wide)
        const int half = bid >> 6;          // 0: x-half of W, 1: y-half
        const int k0   = kc * 32;
        const int n0   = nt * 64;
        const int off  = half * DIMC;

        // embed tile: Es[m][kk] = embed(m)[k0+kk]
        // col c<256: sin(m / 1000^((2c+1)/512));  c>=256: cos(m / 1000^((2(c-256))/512))
        #pragma unroll
        for (int e = t; e < 64 * 32; e += 256) {
            int kk = e & 31, m = e >> 5;
            int c = k0 + kk;
            float z = (float)m;
            float val;
            if (c < 256) {
                float expo = (float)(2 * c + 1) * (1.0f / 512.0f);
                val = sinf(z * expf(-expo * 6.907755278982137f));
            } else {
                float expo = (float)(2 * (c - 256)) * (1.0f / 512.0f);
                val = cosf(z * expf(-expo * 6.907755278982137f));
            }
            Es[m][kk] = val;
        }
        // stage W tile (transposed): rows n0..n0+63, cols k0..k0+31
        #pragma unroll
        for (int e = t; e < 64 * 32; e += 256) {
            int kk = e & 31, i = e >> 5;
            Ws[kk][i] = W[(size_t)(n0 + i) * (2 * DIMC) + off + k0 + kk];
        }
        __syncthreads();

        const int tx = t & 15, ty = t >> 4;
        const int mb = ty * 4, nb = tx * 4;

        float acc[4][4] = {};
        #pragma unroll 8
        for (int k = 0; k < 32; k++) {
            float4 b = *(const float4*)&Ws[k][nb];
            float a0 = Es[mb + 0][k];
            float a1 = Es[mb + 1][k];
            float a2 = Es[mb + 2][k];
            float a3 = Es[mb + 3][k];
            acc[0][0] += a0 * b.x; acc[0][1] += a0 * b.y; acc[0][2] += a0 * b.z; acc[0][3] += a0 * b.w;
            acc[1][0] += a1 * b.x; acc[1][1] += a1 * b.y; acc[1][2] += a1 * b.z; acc[1][3] += a1 * b.w;
            acc[2][0] += a2 * b.x; acc[2][1] += a2 * b.y; acc[2][2] += a2 * b.z; acc[2][3] += a2 * b.w;
            acc[3][0] += a3 * b.x; acc[3][1] += a3 * b.y; acc[3][2] += a3 * b.z; acc[3][3] += a3 * b.w;
        }

        const int rbase = half * 64 + mb;
        #pragma unroll
        for (int i = 0; i < 4; i++)
            #pragma unroll
            for (int j = 0; j < 4; j++)
                atomicAdd(&g_C[rbase + i][n0 + nb + j], acc[i][j]);

        __threadfence();        // all threads: make atomics visible device-wide
        __syncthreads();
        if (t == 0) atomicAdd(&g_gemm_done, 1u);   // release this tile
    }

    // ---------------- Grid barrier: wait for all 128 gemm tiles ----------------
    if (t == 0) {
        while (atomicAdd(&g_gemm_done, 0u) < (unsigned)GEMM_TILES) { }
    }
    __syncthreads();
    __threadfence();   // acquire-side fence before reading g_C

    // ---------------- Phase 2: broadcast write  out[b][h][w][o] = C[h][o]+C[64+w][o]
    const int q   = t & 63;    // float4 index within 256-wide row
    const int sub = t >> 6;    // which of 4 pairs in this group
    const size_t bstride = (size_t)HH * HH * ODIM;   // per-batch stride (1M floats)

    for (int it = bid; it < NPAIR_GROUPS; it += nblocks) {
        int pg = it * 4 + sub;           // pair index 0..4095
        int h = pg >> 6, w = pg & 63;

        float4 a = *(const float4*)&g_C[h][q * 4];
        float4 b = *(const float4*)&g_C[64 + w][q * 4];
        float4 v;
        v.x = a.x + b.x; v.y = a.y + b.y; v.z = a.z + b.z; v.w = a.w + b.w;

        size_t base = ((size_t)pg * ODIM) + (size_t)q * 4;
        #pragma unroll
        for (int bt = 0; bt < BATCH; bt++)
            *(float4*)&out[base + (size_t)bt * bstride] = v;
    }

    // ---------------- Epilogue: last block re-zeroes C, resets flag ------------
    __syncthreads();
    __shared__ unsigned int ticket;
    if (t == 0) ticket = atomicAdd(&g_end_cnt, 1u);
    __syncthreads();

    if (ticket == (unsigned)(nblocks - 1)) {
        // Every block (including all their g_C reads) has arrived -> safe to zero.
        float4 z4 = make_float4(0.f, 0.f, 0.f, 0.f);
        float4* cp = (float4*)g_C;
        #pragma unroll
        for (int i = t; i < (2 * HH * ODIM) / 4; i += 256)
            cp[i] = z4;
        __syncthreads();
        if (t == 0) {
            __threadfence();
            g_gemm_done = 0;           // visible to next replay via kernel boundary
        }
    }
}

// ---------------------------------------------------------------------------
extern "C" void kernel_launch(void* const* d_in, const int* in_sizes, int n_in,
                              void* d_out, int out_size) {
    const float* W = (const float*)d_in[0];   // W_im: (256, 1024) fp32
    float* out = (float*)d_out;               // (8, 64, 64, 256, 1) fp32

    // Size grid to guaranteed co-residency (spin barrier must not deadlock).
    int dev = 0;
    cudaGetDevice(&dev);
    int nsm = 0;
    cudaDeviceGetAttribute(&nsm, cudaDevAttrMultiProcessorCount, dev);
    int occ = 0;
    cudaOccupancyMaxActiveBlocksPerMultiprocessor(&occ, k_fused, 256, 0);
    int nblocks = nsm * occ;
    if (nblocks > NPAIR_GROUPS) nblocks = NPAIR_GROUPS;   // no need for more
    if (nblocks < GEMM_TILES)   nblocks = GEMM_TILES;     // need >=128 (occ>=6 guarantees ~888)

    k_fused<<<nblocks, 256>>>(W, out, nblocks);
}

// round 4
// speedup vs baseline: 1.2243x; 1.2243x over previous
#include <cuda_runtime.h>
#include <math.h>

#define HH    64
#define DIMC  512     // per-axis sinusoid width
#define ODIM  256     // output dim
#define BATCH 8

// C[r][o]: r<64 -> A[h][o] (W cols 0:512), r>=64 -> B[w][o] (W cols 512:1024)
// Static-zero at load; k2's epilogue re-zeroes it after each use, so every
// kernel_launch (correctness run, capture, each replay) sees C == 0 on entry.
__device__ float        g_C[2 * HH][ODIM];
__device__ unsigned int g_end_cnt;              // k2 exit tickets (reset by last block)

// ---------------------------------------------------------------------------
// k1: fused embed + split-K GEMM.
//   C[half*64+m][o] += sum_{k in chunk} embed(m)[k] * W[o][half*512 + k]
// grid: (16 k-chunks of 32, 4 n-tiles of 64, 2 halves) = 128 blocks, 256 thr.
// embed col c<256: sin(m / 1000^((2c+1)/512)); c>=256: cos(m / 1000^((2(c-256))/512))
// ---------------------------------------------------------------------------
__global__ __launch_bounds__(256) void k1_embed_gemm(const float* __restrict__ W) {
    const int k0   = blockIdx.x * 32;
    const int n0   = blockIdx.y * 64;
    const int half = blockIdx.z;
    const int off  = half * DIMC;

    __shared__ float fr[32];        // per-column frequency for this k-chunk
    __shared__ float Es[64][36];    // [m][k] padded
    __shared__ float Ws[32][68];    // [k][n] padded, float4-aligned rows

    const int t = threadIdx.x;

    if (t < 32) {
        int c = k0 + t;
        float expo = (c < 256) ? (float)(2 * c + 1) * (1.0f / 512.0f)
                               : (float)(2 * (c - 256)) * (1.0f / 512.0f);
        fr[t] = expf(-expo * 6.907755278982137f);   // 1000^(-expo)
    }
    __syncthreads();

    // embed tile: Es[m][kk], 2048 values, 8 per thread
    #pragma unroll
    for (int e = t; e < 64 * 32; e += 256) {
        int kk = e & 31, m = e >> 5;
        float zf = (float)m * fr[kk];
        Es[m][kk] = (k0 + kk < 256) ? sinf(zf) : cosf(zf);
    }
    // stage W tile (transposed): rows n0..n0+63, cols k0..k0+31, coalesced over k
    #pragma unroll
    for (int e = t; e < 64 * 32; e += 256) {
        int kk = e & 31, i = e >> 5;
        Ws[kk][i] = W[(size_t)(n0 + i) * (2 * DIMC) + off + k0 + kk];
    }
    __syncthreads();

    const int tx = t & 15, ty = t >> 4;    // 16 x 16 threads
    const int mb = ty * 4, nb = tx * 4;    // 4x4 micro-tile

    float acc[4][4] = {};
    #pragma unroll 8
    for (int k = 0; k < 32; k++) {
        float4 b = *(const float4*)&Ws[k][nb];
        float a0 = Es[mb + 0][k];
        float a1 = Es[mb + 1][k];
        float a2 = Es[mb + 2][k];
        float a3 = Es[mb + 3][k];
        acc[0][0] += a0 * b.x; acc[0][1] += a0 * b.y; acc[0][2] += a0 * b.z; acc[0][3] += a0 * b.w;
        acc[1][0] += a1 * b.x; acc[1][1] += a1 * b.y; acc[1][2] += a1 * b.z; acc[1][3] += a1 * b.w;
        acc[2][0] += a2 * b.x; acc[2][1] += a2 * b.y; acc[2][2] += a2 * b.z; acc[2][3] += a2 * b.w;
        acc[3][0] += a3 * b.x; acc[3][1] += a3 * b.y; acc[3][2] += a3 * b.z; acc[3][3] += a3 * b.w;
    }

    const int rbase = half * 64 + mb;
    #pragma unroll
    for (int i = 0; i < 4; i++)
        #pragma unroll
        for (int j = 0; j < 4; j++)
            atomicAdd(&g_C[rbase + i][n0 + nb + j], acc[i][j]);
    // visibility to k2 comes from the kernel boundary — no fence needed
}

// ---------------------------------------------------------------------------
// k2: out[b][h][w][o] = C[h][o] + C[64+w][o], broadcast over b (8x).
// 1024 blocks x 256 threads; block handles 4 (h,w) pairs; each thread one
// float4 of the 256-wide row, stored 8 times. Fully coalesced 512B/warp.
// Epilogue: last block to finish re-zeroes g_C for the next replay.
// ---------------------------------------------------------------------------
__global__ __launch_bounds__(256) void k2_write(float* __restrict__ out) {
    const int t  = threadIdx.x;
    const int pg = blockIdx.x * 4 + (t >> 6);   // pair index 0..4095
    const int q  = t & 63;                      // float4 index within row
    const int h  = pg >> 6;
    const int w  = pg & 63;

    float4 a = *(const float4*)&g_C[h][q * 4];
    float4 b = *(const float4*)&g_C[64 + w][q * 4];
    float4 v;
    v.x = a.x + b.x; v.y = a.y + b.y; v.z = a.z + b.z; v.w = a.w + b.w;

    size_t base = (((size_t)h * 64 + w) * ODIM) + (size_t)q * 4;
    const size_t bstride = (size_t)HH * HH * ODIM;   // per-batch stride
    #pragma unroll
    for (int bt = 0; bt < BATCH; bt++)
        *(float4*)&out[base + (size_t)bt * bstride] = v;

    // ---- epilogue: last-arriving block zeroes C and resets the counter ----
    __syncthreads();                       // all g_C reads in this block done
    __shared__ unsigned int ticket;
    if (t == 0) ticket = atomicAdd(&g_end_cnt, 1u);
    __syncthreads();

    if (ticket == (unsigned)(gridDim.x - 1)) {
        float4 z4 = make_float4(0.f, 0.f, 0.f, 0.f);
        float4* cp = (float4*)g_C;
        #pragma unroll
        for (int i = t; i < (2 * HH * ODIM) / 4; i += 256)
            cp[i] = z4;
        if (t == 0) g_end_cnt = 0;         // ordered vs next launch by kernel boundary
    }
}

// ---------------------------------------------------------------------------
extern "C" void kernel_launch(void* const* d_in, const int* in_sizes, int n_in,
                              void* d_out, int out_size) {
    const float* W = (const float*)d_in[0];   // W_im: (256, 1024) fp32
    float* out = (float*)d_out;               // (8, 64, 64, 256, 1) fp32

    dim3 g1(16, 4, 2);
    k1_embed_gemm<<<g1, 256>>>(W);
    k2_write<<<1024, 256>>>(out);
}